// round 12
// baseline (speedup 1.0000x reference)
#include <cuda_runtime.h>
#include <math.h>

#define BLOCK 32
#define NSH 81   // sum(2l+1), l=0..8

// Real spherical harmonics (e3nn SphericalHarmonicsAlphaBeta, l=0..8, mul=1).
// out[n, l*l + l + m] = P̄_{l,|m|}(cos b) * sin(b)^|m| * A_m(a)
//   A_m = 1 (m=0), sqrt(2)*cos(m a) (m>0), sqrt(2)*sin(|m| a) (m<0)
// P̄ via stable fully-normalized ALF recurrences (no Condon-Shortley phase).
// One warp per CTA; 32x81 smem tile (stride 81 -> conflict-free); writeback
// with evict-first (.cs) 256-bit stores, NOT unrolled (keeps regs ~50 —
// R6 showed full unroll blows regs to 90 and regresses). .cs policy is
// load-bearing (R8/R11: WB and .wt both cost ~7 us of inter-replay L2
// interference). Inputs use default cached loads (R9: .cs loads regress).
__global__ __launch_bounds__(BLOCK)
void sh_ab_kernel(const float* __restrict__ alpha,
                  const float* __restrict__ beta,
                  float* __restrict__ out, int n)
{
    __shared__ __align__(32) float tile[BLOCK * NSH];   // 10368 B

    const int lane = threadIdx.x;
    const int point = blockIdx.x * BLOCK + lane;

    float a = 0.f, b = 0.f;
    if (point < n) { a = alpha[point]; b = beta[point]; }

    float sa, ca, sb, cb;
    __sincosf(a, &sa, &ca);
    __sincosf(b, &sb, &cb);
    const float z = cb;   // polynomial variable
    const float y = sb;   // sin(beta) >= 0 on [0, pi]

    // cos(m a), sin(m a) for m=0..8 via Chebyshev recurrence
    float cm[9], sn[9];
    cm[0] = 1.f; sn[0] = 0.f;
    cm[1] = ca;  sn[1] = sa;
    const float t2 = 2.f * ca;
#pragma unroll
    for (int m = 2; m <= 8; ++m) {
        cm[m] = t2 * cm[m-1] - cm[m-2];
        sn[m] = t2 * sn[m-1] - sn[m-2];
    }

    const float SQ2 = 1.41421356237309515f;
    float* row = &tile[lane * NSH];

    // m-major sweep: tiny live register set per column
    float pmm = 0.28209479177387814f;   // P̄_00 = sqrt(1/4pi)
#pragma unroll
    for (int m = 0; m <= 8; ++m) {
        if (m > 0)
            pmm *= sqrtf((2.f*m + 1.f) / (2.f*m)) * y;   // sectoral step

        const float Ac = (m == 0) ? 1.f : SQ2 * cm[m];
        const float As = SQ2 * sn[m];

        // l = m
        float plm2 = pmm;
        {
            const int l = m;
            row[l*l + l + m] = plm2 * Ac;
            if (m > 0) row[l*l + l - m] = plm2 * As;
        }
        if (m < 8) {
            // l = m+1
            float plm1 = sqrtf(2.f*m + 3.f) * z * pmm;
            {
                const int l = m + 1;
                row[l*l + l + m] = plm1 * Ac;
                if (m > 0) row[l*l + l - m] = plm1 * As;
            }
            // l = m+2 .. 8
#pragma unroll
            for (int l = m + 2; l <= 8; ++l) {
                const float al = sqrtf((4.f*l*l - 1.f) / (float)(l*l - m*m));
                const float bl = sqrtf((float)((l-1)*(l-1) - m*m) /
                                       (4.f*(l-1)*(l-1) - 1.f));
                const float pl = al * (z * plm1 - bl * plm2);
                row[l*l + l + m] = pl * Ac;
                if (m > 0) row[l*l + l - m] = pl * As;
                plm2 = plm1; plm1 = pl;
            }
        }
    }

    __syncwarp();

    // Evict-first writeback: 324 float8 (=648 float4); 10 float8/lane + tail
    const long long base = (long long)blockIdx.x * (BLOCK * NSH);
    const int remaining = n - blockIdx.x * BLOCK;
    if (remaining >= BLOCK) {
        float* dst = out + base;
        const float4* src4 = reinterpret_cast<const float4*>(tile);
#pragma unroll 2
        for (int k = 0; k < 10; ++k) {
            const int i = k * 32 + lane;            // float8 index 0..319
            const float4 lo = src4[2*i];
            const float4 hi = src4[2*i + 1];
            asm volatile(
                "st.global.cs.v8.f32 [%0], {%1,%2,%3,%4,%5,%6,%7,%8};"
                :: "l"(dst + 8LL*i),
                   "f"(lo.x), "f"(lo.y), "f"(lo.z), "f"(lo.w),
                   "f"(hi.x), "f"(hi.y), "f"(hi.z), "f"(hi.w)
                : "memory");
        }
        if (lane < 8) {                              // float4 indices 640..647
            const int i4 = 640 + lane;
            __stcs(reinterpret_cast<float4*>(dst) + i4, src4[i4]);
        }
    } else {
        const int floats = (remaining > 0 ? remaining : 0) * NSH;
        for (int i = lane; i < floats; i += BLOCK)
            __stcs(&out[base + i], tile[i]);
    }
}

extern "C" void kernel_launch(void* const* d_in, const int* in_sizes, int n_in,
                              void* d_out, int out_size)
{
    const float* alpha = (const float*)d_in[0];
    const float* beta  = (const float*)d_in[1];
    float* out = (float*)d_out;
    const int n = in_sizes[0];
    const int grid = (n + BLOCK - 1) / BLOCK;
    sh_ab_kernel<<<grid, BLOCK>>>(alpha, beta, out, n);
}

// round 13
// speedup vs baseline: 1.1617x; 1.1617x over previous
#include <cuda_runtime.h>
#include <math.h>

#define BLOCK 32
#define NSH 81   // sum(2l+1), l=0..8

// FINAL (R7 winner, restored): Real spherical harmonics
// (e3nn SphericalHarmonicsAlphaBeta, l=0..8, mul=1).
// out[n, l*l + l + m] = P̄_{l,|m|}(cos b) * sin(b)^|m| * A_m(a)
//   A_m = 1 (m=0), sqrt(2)*cos(m a) (m>0), sqrt(2)*sin(|m| a) (m<0)
// P̄ via stable fully-normalized ALF recurrences (no Condon-Shortley phase).
// One warp per CTA: 32-point tile staged in 10.1 KB smem (stride-81 rows,
// 81 odd -> conflict-free), flushed as coalesced float4 evict-first (.cs)
// streaming stores.
// Session-mapped design space (do not revisit):
//  - .cs stores uniquely optimal: default-WB +7us, .wt +7us (inter-replay
//    L2 flush interference, invisible to ncu -c 1); .cs input loads +7us.
//  - 256-bit st.global.cs.v8 regresses with both high regs (R6) and low
//    regs (R12) — L1 wavefronts don't shrink, store chain serializes.
//  - TMA bulk store: same L1 path, worse retirement (R3).
//  - persistent grid: serializes compute/store phases per warp (R5).
//  - BLOCK 32 ≈ 64 > 128; one warp/CTA best.
// 332 MB @ ~6.7 TB/s timed ≈ 84% of spec HBM write bandwidth.
__global__ __launch_bounds__(BLOCK)
void sh_ab_kernel(const float* __restrict__ alpha,
                  const float* __restrict__ beta,
                  float* __restrict__ out, int n)
{
    __shared__ __align__(16) float tile[BLOCK * NSH];   // 10368 B

    const int lane = threadIdx.x;
    const int point = blockIdx.x * BLOCK + lane;

    float a = 0.f, b = 0.f;
    if (point < n) { a = alpha[point]; b = beta[point]; }

    float sa, ca, sb, cb;
    __sincosf(a, &sa, &ca);
    __sincosf(b, &sb, &cb);
    const float z = cb;   // polynomial variable
    const float y = sb;   // sin(beta) >= 0 on [0, pi]

    // cos(m a), sin(m a) for m=0..8 via Chebyshev recurrence
    float cm[9], sn[9];
    cm[0] = 1.f; sn[0] = 0.f;
    cm[1] = ca;  sn[1] = sa;
    const float t2 = 2.f * ca;
#pragma unroll
    for (int m = 2; m <= 8; ++m) {
        cm[m] = t2 * cm[m-1] - cm[m-2];
        sn[m] = t2 * sn[m-1] - sn[m-2];
    }

    const float SQ2 = 1.41421356237309515f;
    float* row = &tile[lane * NSH];

    // m-major sweep: tiny live register set per column
    float pmm = 0.28209479177387814f;   // P̄_00 = sqrt(1/4pi)
#pragma unroll
    for (int m = 0; m <= 8; ++m) {
        if (m > 0)
            pmm *= sqrtf((2.f*m + 1.f) / (2.f*m)) * y;   // sectoral step

        const float Ac = (m == 0) ? 1.f : SQ2 * cm[m];
        const float As = SQ2 * sn[m];

        // l = m
        float plm2 = pmm;
        {
            const int l = m;
            row[l*l + l + m] = plm2 * Ac;
            if (m > 0) row[l*l + l - m] = plm2 * As;
        }
        if (m < 8) {
            // l = m+1
            float plm1 = sqrtf(2.f*m + 3.f) * z * pmm;
            {
                const int l = m + 1;
                row[l*l + l + m] = plm1 * Ac;
                if (m > 0) row[l*l + l - m] = plm1 * As;
            }
            // l = m+2 .. 8
#pragma unroll
            for (int l = m + 2; l <= 8; ++l) {
                const float al = sqrtf((4.f*l*l - 1.f) / (float)(l*l - m*m));
                const float bl = sqrtf((float)((l-1)*(l-1) - m*m) /
                                       (4.f*(l-1)*(l-1) - 1.f));
                const float pl = al * (z * plm1 - bl * plm2);
                row[l*l + l + m] = pl * Ac;
                if (m > 0) row[l*l + l - m] = pl * As;
                plm2 = plm1; plm1 = pl;
            }
        }
    }

    __syncwarp();

    // Coalesced streaming writeback: 32*81 floats = 648 float4
    const long long base = (long long)blockIdx.x * (BLOCK * NSH);
    const int remaining = n - blockIdx.x * BLOCK;
    if (remaining >= BLOCK) {
        float4* dst = reinterpret_cast<float4*>(out + base);
        const float4* src = reinterpret_cast<const float4*>(tile);
#pragma unroll 5
        for (int i = lane; i < (BLOCK * NSH) / 4; i += BLOCK)
            __stcs(&dst[i], src[i]);
    } else {
        const int floats = (remaining > 0 ? remaining : 0) * NSH;
        for (int i = lane; i < floats; i += BLOCK)
            __stcs(&out[base + i], tile[i]);
    }
}

extern "C" void kernel_launch(void* const* d_in, const int* in_sizes, int n_in,
                              void* d_out, int out_size)
{
    const float* alpha = (const float*)d_in[0];
    const float* beta  = (const float*)d_in[1];
    float* out = (float*)d_out;
    const int n = in_sizes[0];
    const int grid = (n + BLOCK - 1) / BLOCK;
    sh_ab_kernel<<<grid, BLOCK>>>(alpha, beta, out, n);
}